// round 2
// baseline (speedup 1.0000x reference)
#include <cuda_runtime.h>
#include <cuda_bf16.h>
#include <cstdint>

#define NROWS 8192
#define BHALF 4096
#define KDIM  128

// Scratch (device globals — no allocation allowed in kernel_launch)
__device__ __nv_bfloat16 g_Xb[NROWS * KDIM];   // bf16 copy of features
__device__ float g_sq[NROWS];                  // |x|^2 from bf16-rounded values
__device__ float g_rowA[NROWS];                // sum over j in [0,4096)
__device__ float g_rowB[NROWS];                // sum over j in [4096,8192)
__device__ float g_logdiag[BHALF];             // log k12(i,i), fp32 path

static __device__ __forceinline__ uint32_t smem_u32(const void* p) {
    return (uint32_t)__cvta_generic_to_shared(p);
}

static __device__ __forceinline__ float rcp_approx(float x) {
    float r;
    asm("rcp.approx.ftz.f32 %0, %1;" : "=f"(r) : "f"(x));
    return r;
}

// ---------------------------------------------------------------------------
// K0: zero the accumulators (graph is replayed — must re-zero every launch)
// ---------------------------------------------------------------------------
__global__ void zero_kernel() {
    int i = blockIdx.x * blockDim.x + threadIdx.x;
    if (i < NROWS) { g_rowA[i] = 0.f; g_rowB[i] = 0.f; }
}

// ---------------------------------------------------------------------------
// K1: convert features -> bf16, compute |x|^2 (from the rounded values).
// One warp per row.
// ---------------------------------------------------------------------------
__global__ void prep_kernel(const float* __restrict__ feat) {
    int wid = threadIdx.x >> 5;
    int lane = threadIdx.x & 31;
    int row = blockIdx.x * 8 + wid;
    if (row >= NROWS) return;
    const float* src = feat + (size_t)row * KDIM;
    __nv_bfloat16* dst = g_Xb + (size_t)row * KDIM;
    float acc = 0.f;
#pragma unroll
    for (int c = 0; c < 4; c++) {
        float v = src[c * 32 + lane];
        __nv_bfloat16 h = __float2bfloat16(v);
        dst[c * 32 + lane] = h;
        float vb = __bfloat162float(h);
        acc = fmaf(vb, vb, acc);
    }
#pragma unroll
    for (int off = 16; off > 0; off >>= 1)
        acc += __shfl_xor_sync(0xffffffff, acc, off);
    if (lane == 0) g_sq[row] = acc;
}

// ---------------------------------------------------------------------------
// K2: main pairwise kernel. CTA = 128x128 tile of the 8192x8192 kernel matrix.
// bf16 mma.sync m16n8k16, fp32 accum, fused Cauchy epilogue + row-sum atomics.
// ---------------------------------------------------------------------------
#define LDS_STRIDE 136   // bf16 elements per smem row: 128 data + 8 pad (272 B)
#define TILE_ELEMS (128 * LDS_STRIDE)
#define PAIR_SMEM_BYTES (2 * TILE_ELEMS * 2)

__global__ void __launch_bounds__(256, 2) pair_kernel() {
    extern __shared__ __align__(16) __nv_bfloat16 smem_bf[];
    __nv_bfloat16* sA = smem_bf;
    __nv_bfloat16* sB = smem_bf + TILE_ELEMS;
    __shared__ float s_a[128];   // 1 + |x_i|^2 for tile rows
    __shared__ float s_b[128];   // |y_j|^2 for tile cols

    const int bi = blockIdx.y;
    const int bj = blockIdx.x;
    const int tid = threadIdx.x;
    const int lane = tid & 31;
    const int wid = tid >> 5;

    // ---- load tiles (128 rows x 256B each, as uint4 chunks) ----
    const uint4* gA = (const uint4*)(g_Xb + (size_t)bi * 128 * KDIM);
    const uint4* gB = (const uint4*)(g_Xb + (size_t)bj * 128 * KDIM);
#pragma unroll
    for (int it = 0; it < 8; it++) {
        int idx = tid + it * 256;       // 0..2047
        int r = idx >> 4, c = idx & 15;
        *(uint4*)&sA[r * LDS_STRIDE + c * 8] = gA[r * 16 + c];
        *(uint4*)&sB[r * LDS_STRIDE + c * 8] = gB[r * 16 + c];
    }
    if (tid < 128) {
        s_a[tid] = 1.f + g_sq[bi * 128 + tid];
        s_b[tid] = g_sq[bj * 128 + tid];
    }
    __syncthreads();

    // ---- warp tiling: 4 (m) x 2 (n); warp tile = 32 x 64 ----
    const int rowbase = (wid & 3) * 32;
    const int colbase = (wid >> 2) * 64;

    float acc[2][8][4];
#pragma unroll
    for (int mi = 0; mi < 2; mi++)
#pragma unroll
        for (int ni = 0; ni < 8; ni++)
#pragma unroll
            for (int r = 0; r < 4; r++) acc[mi][ni][r] = 0.f;

    const int lr = lane & 15;
    const int lc = lane >> 4;
    uint32_t aoff[2], boff[4];
#pragma unroll
    for (int mi = 0; mi < 2; mi++)
        aoff[mi] = smem_u32(&sA[(rowbase + mi * 16 + lr) * LDS_STRIDE + lc * 8]);
#pragma unroll
    for (int nq = 0; nq < 4; nq++)
        boff[nq] = smem_u32(&sB[(colbase + nq * 16 + lr) * LDS_STRIDE + lc * 8]);

#pragma unroll
    for (int ks = 0; ks < 8; ks++) {
        uint32_t a[2][4];
        uint32_t b[8][2];
#pragma unroll
        for (int mi = 0; mi < 2; mi++) {
            asm volatile("ldmatrix.sync.aligned.m8n8.x4.shared.b16 {%0,%1,%2,%3}, [%4];"
                         : "=r"(a[mi][0]), "=r"(a[mi][1]), "=r"(a[mi][2]), "=r"(a[mi][3])
                         : "r"(aoff[mi] + ks * 32));
        }
#pragma unroll
        for (int nq = 0; nq < 4; nq++) {
            uint32_t r0, r1, r2, r3;
            asm volatile("ldmatrix.sync.aligned.m8n8.x4.shared.b16 {%0,%1,%2,%3}, [%4];"
                         : "=r"(r0), "=r"(r1), "=r"(r2), "=r"(r3)
                         : "r"(boff[nq] + ks * 32));
            b[nq * 2 + 0][0] = r0; b[nq * 2 + 1][0] = r1;
            b[nq * 2 + 0][1] = r2; b[nq * 2 + 1][1] = r3;
        }
#pragma unroll
        for (int mi = 0; mi < 2; mi++)
#pragma unroll
            for (int ni = 0; ni < 8; ni++) {
                asm volatile(
                    "mma.sync.aligned.m16n8k16.row.col.f32.bf16.bf16.f32 "
                    "{%0,%1,%2,%3}, {%4,%5,%6,%7}, {%8,%9}, {%0,%1,%2,%3};"
                    : "+f"(acc[mi][ni][0]), "+f"(acc[mi][ni][1]),
                      "+f"(acc[mi][ni][2]), "+f"(acc[mi][ni][3])
                    : "r"(a[mi][0]), "r"(a[mi][1]), "r"(a[mi][2]), "r"(a[mi][3]),
                      "r"(b[ni][0]), "r"(b[ni][1]));
            }
    }

    // ---- epilogue: k = 1 / max(1 + |x|^2 + |y|^2 - 2 x.y, 1), row sums ----
    const int qr = lane >> 2;          // row within 8
    const int qc = (lane & 3) * 2;     // col pair within 8
    float rs[2][2] = {{0.f, 0.f}, {0.f, 0.f}};   // [mi][row-half]
#pragma unroll
    for (int mi = 0; mi < 2; mi++) {
        float a0 = s_a[rowbase + mi * 16 + qr];
        float a1 = s_a[rowbase + mi * 16 + qr + 8];
#pragma unroll
        for (int ni = 0; ni < 8; ni++) {
            float b0 = s_b[colbase + ni * 8 + qc];
            float b1 = s_b[colbase + ni * 8 + qc + 1];
            float d00 = fmaf(acc[mi][ni][0], -2.f, a0 + b0);
            float d01 = fmaf(acc[mi][ni][1], -2.f, a0 + b1);
            float d10 = fmaf(acc[mi][ni][2], -2.f, a1 + b0);
            float d11 = fmaf(acc[mi][ni][3], -2.f, a1 + b1);
            rs[mi][0] += rcp_approx(fmaxf(d00, 1.f)) + rcp_approx(fmaxf(d01, 1.f));
            rs[mi][1] += rcp_approx(fmaxf(d10, 1.f)) + rcp_approx(fmaxf(d11, 1.f));
        }
    }
    // reduce across the 4 lanes of each quad (they share the same rows)
#pragma unroll
    for (int mi = 0; mi < 2; mi++)
#pragma unroll
        for (int h = 0; h < 2; h++) {
            rs[mi][h] += __shfl_xor_sync(0xffffffff, rs[mi][h], 1);
            rs[mi][h] += __shfl_xor_sync(0xffffffff, rs[mi][h], 2);
        }
    if ((lane & 3) == 0) {
        float* dst = (bj < 32) ? g_rowA : g_rowB;
#pragma unroll
        for (int mi = 0; mi < 2; mi++) {
            int r0 = bi * 128 + rowbase + mi * 16 + qr;
            atomicAdd(dst + r0, rs[mi][0]);
            atomicAdd(dst + r0 + 8, rs[mi][1]);
        }
    }
}

// ---------------------------------------------------------------------------
// K3: z12 diagonal in full fp32 from original features (pos term).
// One warp per i.
// ---------------------------------------------------------------------------
__global__ void diag_kernel(const float* __restrict__ feat) {
    int wid = threadIdx.x >> 5;
    int lane = threadIdx.x & 31;
    int i = blockIdx.x * 8 + wid;
    if (i >= BHALF) return;
    const float* f1 = feat + (size_t)i * KDIM;
    const float* f2 = feat + (size_t)(i + BHALF) * KDIM;
    float sd = 0.f, s1 = 0.f, s2 = 0.f;
#pragma unroll
    for (int c = 0; c < 4; c++) {
        float v1 = f1[c * 32 + lane];
        float v2 = f2[c * 32 + lane];
        sd = fmaf(v1, v2, sd);
        s1 = fmaf(v1, v1, s1);
        s2 = fmaf(v2, v2, s2);
    }
#pragma unroll
    for (int off = 16; off > 0; off >>= 1) {
        sd += __shfl_xor_sync(0xffffffff, sd, off);
        s1 += __shfl_xor_sync(0xffffffff, s1, off);
        s2 += __shfl_xor_sync(0xffffffff, s2, off);
    }
    if (lane == 0) {
        float d2 = fmaxf(s1 + s2 - 2.f * sd, 0.f);
        g_logdiag[i] = -log1pf(d2);   // log(1/(1+d2))
    }
}

// ---------------------------------------------------------------------------
// K4: final scalar.  neg = mean(log(A+B-1)) over all 8192 rows
//     combine: result = neg - pos
// ---------------------------------------------------------------------------
__global__ void finalize_kernel(float* out) {
    const int tid = threadIdx.x;
    float an = 0.f, ap = 0.f;
    for (int i = tid; i < NROWS; i += 1024)
        an += logf(g_rowA[i] + g_rowB[i] - 1.0f);
    for (int i = tid; i < BHALF; i += 1024)
        ap += g_logdiag[i];
#pragma unroll
    for (int off = 16; off > 0; off >>= 1) {
        an += __shfl_xor_sync(0xffffffff, an, off);
        ap += __shfl_xor_sync(0xffffffff, ap, off);
    }
    __shared__ float sn[32], sp[32];
    int wid = tid >> 5, lane = tid & 31;
    if (lane == 0) { sn[wid] = an; sp[wid] = ap; }
    __syncthreads();
    if (wid == 0) {
        an = sn[lane];
        ap = sp[lane];
#pragma unroll
        for (int off = 16; off > 0; off >>= 1) {
            an += __shfl_xor_sync(0xffffffff, an, off);
            ap += __shfl_xor_sync(0xffffffff, ap, off);
        }
        if (lane == 0) {
            float neg = an / (2.0f * (float)BHALF);
            float pos = ap / (float)BHALF;
            out[0] = neg - pos;   // -(pos - neg)
        }
    }
}

// ---------------------------------------------------------------------------
extern "C" void kernel_launch(void* const* d_in, const int* in_sizes, int n_in,
                              void* d_out, int out_size) {
    const float* feat = (const float*)d_in[0];
    float* out = (float*)d_out;

    cudaFuncSetAttribute(pair_kernel,
                         cudaFuncAttributeMaxDynamicSharedMemorySize,
                         PAIR_SMEM_BYTES);

    zero_kernel<<<(NROWS + 255) / 256, 256>>>();
    prep_kernel<<<NROWS / 8, 256>>>(feat);
    diag_kernel<<<BHALF / 8, 256>>>(feat);
    dim3 grid(64, 64);
    pair_kernel<<<grid, 256, PAIR_SMEM_BYTES>>>();
    finalize_kernel<<<1, 1024>>>(out);
}

// round 3
// speedup vs baseline: 1.1966x; 1.1966x over previous
#include <cuda_runtime.h>
#include <cuda_bf16.h>
#include <cstdint>
#include <cmath>

#define NROWS 8192
#define BHALF 4096
#define KDIM  128
#define NBLK  64                 // 8192 / 128
#define NTILES (NBLK * (NBLK + 1) / 2)   // 2080 upper-triangle tiles

// Scratch (device globals — no allocation allowed in kernel_launch)
__device__ __nv_bfloat16 g_Xb[NROWS * KDIM];   // bf16 copy of features
__device__ float g_sq[NROWS];                  // |x|^2 from bf16-rounded values
__device__ float g_row[NROWS];                 // full row sums of the 8192x8192 kernel matrix
__device__ float g_logdiag[BHALF];             // log k12(i,i), fp32 path

static __device__ __forceinline__ uint32_t smem_u32(const void* p) {
    return (uint32_t)__cvta_generic_to_shared(p);
}

static __device__ __forceinline__ float rcp_approx(float x) {
    float r;
    asm("rcp.approx.ftz.f32 %0, %1;" : "=f"(r) : "f"(x));
    return r;
}

// ---------------------------------------------------------------------------
// K1: convert features -> bf16, compute |x|^2 (from rounded values), zero g_row.
// One warp per row.
// ---------------------------------------------------------------------------
__global__ void prep_kernel(const float* __restrict__ feat) {
    int wid = threadIdx.x >> 5;
    int lane = threadIdx.x & 31;
    int row = blockIdx.x * 8 + wid;
    if (row >= NROWS) return;
    const float* src = feat + (size_t)row * KDIM;
    __nv_bfloat16* dst = g_Xb + (size_t)row * KDIM;
    float acc = 0.f;
#pragma unroll
    for (int c = 0; c < 4; c++) {
        float v = src[c * 32 + lane];
        __nv_bfloat16 h = __float2bfloat16(v);
        dst[c * 32 + lane] = h;
        float vb = __bfloat162float(h);
        acc = fmaf(vb, vb, acc);
    }
#pragma unroll
    for (int off = 16; off > 0; off >>= 1)
        acc += __shfl_xor_sync(0xffffffff, acc, off);
    if (lane == 0) { g_sq[row] = acc; g_row[row] = 0.f; }
}

// ---------------------------------------------------------------------------
// K2: main pairwise kernel, UPPER-TRIANGLE tiles only (symmetry).
// CTA = 128x128 tile (bi <= bj). Contributes row sums to block bi's rows and
// (for bi != bj) column sums to block bj's rows.
// ---------------------------------------------------------------------------
#define LDS_STRIDE 136   // bf16 elements per smem row: 128 data + 8 pad (272 B)
#define TILE_ELEMS (128 * LDS_STRIDE)
#define PAIR_SMEM_BYTES (2 * TILE_ELEMS * 2)

__global__ void __launch_bounds__(256, 2) pair_kernel() {
    extern __shared__ __align__(16) __nv_bfloat16 smem_bf[];
    __nv_bfloat16* sA = smem_bf;
    __nv_bfloat16* sB = smem_bf + TILE_ELEMS;
    __shared__ float s_a[128];   // 1 + |x_i|^2 for tile rows
    __shared__ float s_b[128];   // |y_j|^2 for tile cols

    // map linear tile id -> (bi, bj), bi <= bj, t = bj*(bj+1)/2 + bi
    const int t = blockIdx.x;
    int bj = (int)((sqrt(8.0 * (double)t + 1.0) - 1.0) * 0.5);
    while ((bj + 1) * (bj + 2) / 2 <= t) bj++;
    while (bj * (bj + 1) / 2 > t) bj--;
    const int bi = t - bj * (bj + 1) / 2;

    const int tid = threadIdx.x;
    const int lane = tid & 31;
    const int wid = tid >> 5;

    // ---- load tiles (128 rows x 256B each, as uint4 chunks) ----
    const uint4* gA = (const uint4*)(g_Xb + (size_t)bi * 128 * KDIM);
    const uint4* gB = (const uint4*)(g_Xb + (size_t)bj * 128 * KDIM);
#pragma unroll
    for (int it = 0; it < 8; it++) {
        int idx = tid + it * 256;       // 0..2047
        int r = idx >> 4, c = idx & 15;
        *(uint4*)&sA[r * LDS_STRIDE + c * 8] = gA[r * 16 + c];
        *(uint4*)&sB[r * LDS_STRIDE + c * 8] = gB[r * 16 + c];
    }
    if (tid < 128) {
        s_a[tid] = 1.f + g_sq[bi * 128 + tid];
        s_b[tid] = g_sq[bj * 128 + tid];
    }
    __syncthreads();

    // ---- warp tiling: 4 (m) x 2 (n); warp tile = 32 x 64 ----
    const int rowbase = (wid & 3) * 32;
    const int colbase = (wid >> 2) * 64;

    float acc[2][8][4];
#pragma unroll
    for (int mi = 0; mi < 2; mi++)
#pragma unroll
        for (int ni = 0; ni < 8; ni++)
#pragma unroll
            for (int r = 0; r < 4; r++) acc[mi][ni][r] = 0.f;

    const int lr = lane & 15;
    const int lc = lane >> 4;
    uint32_t aoff[2], boff[4];
#pragma unroll
    for (int mi = 0; mi < 2; mi++)
        aoff[mi] = smem_u32(&sA[(rowbase + mi * 16 + lr) * LDS_STRIDE + lc * 8]);
#pragma unroll
    for (int nq = 0; nq < 4; nq++)
        boff[nq] = smem_u32(&sB[(colbase + nq * 16 + lr) * LDS_STRIDE + lc * 8]);

#pragma unroll
    for (int ks = 0; ks < 8; ks++) {
        uint32_t a[2][4];
        uint32_t b[8][2];
#pragma unroll
        for (int mi = 0; mi < 2; mi++) {
            asm volatile("ldmatrix.sync.aligned.m8n8.x4.shared.b16 {%0,%1,%2,%3}, [%4];"
                         : "=r"(a[mi][0]), "=r"(a[mi][1]), "=r"(a[mi][2]), "=r"(a[mi][3])
                         : "r"(aoff[mi] + ks * 32));
        }
#pragma unroll
        for (int nq = 0; nq < 4; nq++) {
            uint32_t r0, r1, r2, r3;
            asm volatile("ldmatrix.sync.aligned.m8n8.x4.shared.b16 {%0,%1,%2,%3}, [%4];"
                         : "=r"(r0), "=r"(r1), "=r"(r2), "=r"(r3)
                         : "r"(boff[nq] + ks * 32));
            b[nq * 2 + 0][0] = r0; b[nq * 2 + 1][0] = r1;
            b[nq * 2 + 0][1] = r2; b[nq * 2 + 1][1] = r3;
        }
#pragma unroll
        for (int mi = 0; mi < 2; mi++)
#pragma unroll
            for (int ni = 0; ni < 8; ni++) {
                asm volatile(
                    "mma.sync.aligned.m16n8k16.row.col.f32.bf16.bf16.f32 "
                    "{%0,%1,%2,%3}, {%4,%5,%6,%7}, {%8,%9}, {%0,%1,%2,%3};"
                    : "+f"(acc[mi][ni][0]), "+f"(acc[mi][ni][1]),
                      "+f"(acc[mi][ni][2]), "+f"(acc[mi][ni][3])
                    : "r"(a[mi][0]), "r"(a[mi][1]), "r"(a[mi][2]), "r"(a[mi][3]),
                      "r"(b[ni][0]), "r"(b[ni][1]));
            }
    }

    // ---- epilogue: k = 1 / max(1 + |x|^2 + |y|^2 - 2 x.y, 1) ----
    // row sums always; column sums too when bi != bj (off-diagonal tile).
    const int qr = lane >> 2;          // row within 8
    const int qc = (lane & 3) * 2;     // col pair within 8
    const bool offdiag = (bi != bj);
    float rs[2][2] = {{0.f, 0.f}, {0.f, 0.f}};   // [mi][row-half]

#pragma unroll
    for (int ni = 0; ni < 8; ni++) {
        float b0 = s_b[colbase + ni * 8 + qc];
        float b1 = s_b[colbase + ni * 8 + qc + 1];
        float cs0 = 0.f, cs1 = 0.f;   // partial column sums for this ni
#pragma unroll
        for (int mi = 0; mi < 2; mi++) {
            float a0 = s_a[rowbase + mi * 16 + qr];
            float a1 = s_a[rowbase + mi * 16 + qr + 8];
            float k00 = rcp_approx(fmaxf(fmaf(acc[mi][ni][0], -2.f, a0 + b0), 1.f));
            float k01 = rcp_approx(fmaxf(fmaf(acc[mi][ni][1], -2.f, a0 + b1), 1.f));
            float k10 = rcp_approx(fmaxf(fmaf(acc[mi][ni][2], -2.f, a1 + b0), 1.f));
            float k11 = rcp_approx(fmaxf(fmaf(acc[mi][ni][3], -2.f, a1 + b1), 1.f));
            rs[mi][0] += k00 + k01;
            rs[mi][1] += k10 + k11;
            cs0 += k00 + k10;
            cs1 += k01 + k11;
        }
        if (offdiag) {
            // reduce across the 8 qr-groups (lane bits 2..4)
            cs0 += __shfl_xor_sync(0xffffffff, cs0, 4);
            cs1 += __shfl_xor_sync(0xffffffff, cs1, 4);
            cs0 += __shfl_xor_sync(0xffffffff, cs0, 8);
            cs1 += __shfl_xor_sync(0xffffffff, cs1, 8);
            cs0 += __shfl_xor_sync(0xffffffff, cs0, 16);
            cs1 += __shfl_xor_sync(0xffffffff, cs1, 16);
            if (lane < 4) {
                int cg = bj * 128 + colbase + ni * 8 + qc;
                atomicAdd(g_row + cg, cs0);
                atomicAdd(g_row + cg + 1, cs1);
            }
        }
    }

    // reduce row sums across the 4 lanes of each quad (same rows)
#pragma unroll
    for (int mi = 0; mi < 2; mi++)
#pragma unroll
        for (int h = 0; h < 2; h++) {
            rs[mi][h] += __shfl_xor_sync(0xffffffff, rs[mi][h], 1);
            rs[mi][h] += __shfl_xor_sync(0xffffffff, rs[mi][h], 2);
        }
    if ((lane & 3) == 0) {
#pragma unroll
        for (int mi = 0; mi < 2; mi++) {
            int r0 = bi * 128 + rowbase + mi * 16 + qr;
            atomicAdd(g_row + r0, rs[mi][0]);
            atomicAdd(g_row + r0 + 8, rs[mi][1]);
        }
    }
}

// ---------------------------------------------------------------------------
// K3: z12 diagonal in full fp32 from original features (pos term).
// One warp per i.
// ---------------------------------------------------------------------------
__global__ void diag_kernel(const float* __restrict__ feat) {
    int wid = threadIdx.x >> 5;
    int lane = threadIdx.x & 31;
    int i = blockIdx.x * 8 + wid;
    if (i >= BHALF) return;
    const float* f1 = feat + (size_t)i * KDIM;
    const float* f2 = feat + (size_t)(i + BHALF) * KDIM;
    float sd = 0.f, s1 = 0.f, s2 = 0.f;
#pragma unroll
    for (int c = 0; c < 4; c++) {
        float v1 = f1[c * 32 + lane];
        float v2 = f2[c * 32 + lane];
        sd = fmaf(v1, v2, sd);
        s1 = fmaf(v1, v1, s1);
        s2 = fmaf(v2, v2, s2);
    }
#pragma unroll
    for (int off = 16; off > 0; off >>= 1) {
        sd += __shfl_xor_sync(0xffffffff, sd, off);
        s1 += __shfl_xor_sync(0xffffffff, s1, off);
        s2 += __shfl_xor_sync(0xffffffff, s2, off);
    }
    if (lane == 0) {
        float d2 = fmaxf(s1 + s2 - 2.f * sd, 0.f);
        g_logdiag[i] = -log1pf(d2);   // log(1/(1+d2))
    }
}

// ---------------------------------------------------------------------------
// K4: final scalar.  neg = mean(log(rowsum - 1)) over all 8192 rows / 2
//     result = neg - pos
// ---------------------------------------------------------------------------
__global__ void finalize_kernel(float* out) {
    const int tid = threadIdx.x;
    float an = 0.f, ap = 0.f;
    for (int i = tid; i < NROWS; i += 1024)
        an += logf(g_row[i] - 1.0f);
    for (int i = tid; i < BHALF; i += 1024)
        ap += g_logdiag[i];
#pragma unroll
    for (int off = 16; off > 0; off >>= 1) {
        an += __shfl_xor_sync(0xffffffff, an, off);
        ap += __shfl_xor_sync(0xffffffff, ap, off);
    }
    __shared__ float sn[32], sp[32];
    int wid = tid >> 5, lane = tid & 31;
    if (lane == 0) { sn[wid] = an; sp[wid] = ap; }
    __syncthreads();
    if (wid == 0) {
        an = sn[lane];
        ap = sp[lane];
#pragma unroll
        for (int off = 16; off > 0; off >>= 1) {
            an += __shfl_xor_sync(0xffffffff, an, off);
            ap += __shfl_xor_sync(0xffffffff, ap, off);
        }
        if (lane == 0) {
            float neg = an / (2.0f * (float)BHALF);
            float pos = ap / (float)BHALF;
            out[0] = neg - pos;   // -(pos - neg)
        }
    }
}

// ---------------------------------------------------------------------------
extern "C" void kernel_launch(void* const* d_in, const int* in_sizes, int n_in,
                              void* d_out, int out_size) {
    const float* feat = (const float*)d_in[0];
    float* out = (float*)d_out;

    cudaFuncSetAttribute(pair_kernel,
                         cudaFuncAttributeMaxDynamicSharedMemorySize,
                         PAIR_SMEM_BYTES);

    prep_kernel<<<NROWS / 8, 256>>>(feat);
    diag_kernel<<<BHALF / 8, 256>>>(feat);
    pair_kernel<<<NTILES, 256, PAIR_SMEM_BYTES>>>();
    finalize_kernel<<<1, 1024>>>(out);
}

// round 4
// speedup vs baseline: 1.3236x; 1.1062x over previous
#include <cuda_runtime.h>
#include <cuda_bf16.h>
#include <cstdint>

#define NROWS 8192
#define BHALF 4096
#define KDIM  128
// super-tiles: 256-row blocks (32) x 128-col blocks (64), bj >= 2*bip
#define NTILES2 1056

// Scratch (device globals — no allocation allowed in kernel_launch)
__device__ __nv_bfloat16 g_Xb[NROWS * KDIM];   // bf16 copy of features
__device__ float g_sq[NROWS];                  // |x|^2 from bf16-rounded values
__device__ float g_row[NROWS];                 // full row sums of 8192x8192 kernel matrix
__device__ float g_logdiag[BHALF];             // log k12(i,i), fp32 path
__device__ float g_part[2];                    // partial sums for finalize
__device__ unsigned int g_cnt;                 // finalize block counter

static __device__ __forceinline__ uint32_t smem_u32(const void* p) {
    return (uint32_t)__cvta_generic_to_shared(p);
}

static __device__ __forceinline__ float rcp_approx(float x) {
    float r;
    asm("rcp.approx.ftz.f32 %0, %1;" : "=f"(r) : "f"(x));
    return r;
}

// ---------------------------------------------------------------------------
// K1: fused prep + diag. One warp per pair (i, i+4096): converts both rows to
// bf16, computes |x|^2 (bf16-rounded, matches pair kernel), fp32 diagonal dot
// for the pos term, zeroes g_row, resets finalize scratch.
// ---------------------------------------------------------------------------
__global__ void prep_kernel(const float* __restrict__ feat) {
    int w = threadIdx.x >> 5;
    int lane = threadIdx.x & 31;
    int p = blockIdx.x * 8 + w;           // 0..4095
    if (blockIdx.x == 0 && threadIdx.x == 0) {
        g_part[0] = 0.f; g_part[1] = 0.f; g_cnt = 0u;
    }
    if (p >= BHALF) return;
    const float* f1 = feat + (size_t)p * KDIM;
    const float* f2 = feat + (size_t)(p + BHALF) * KDIM;
    __nv_bfloat16* d1 = g_Xb + (size_t)p * KDIM;
    __nv_bfloat16* d2 = g_Xb + (size_t)(p + BHALF) * KDIM;
    float sb1 = 0.f, sb2 = 0.f;           // bf16-rounded norms (for pair kernel)
    float t1 = 0.f, t2 = 0.f, sd = 0.f;   // fp32 norms + dot (for pos term)
#pragma unroll
    for (int c = 0; c < 4; c++) {
        float v1 = f1[c * 32 + lane];
        float v2 = f2[c * 32 + lane];
        __nv_bfloat16 h1 = __float2bfloat16(v1);
        __nv_bfloat16 h2 = __float2bfloat16(v2);
        d1[c * 32 + lane] = h1;
        d2[c * 32 + lane] = h2;
        float b1 = __bfloat162float(h1);
        float b2 = __bfloat162float(h2);
        sb1 = fmaf(b1, b1, sb1);
        sb2 = fmaf(b2, b2, sb2);
        t1 = fmaf(v1, v1, t1);
        t2 = fmaf(v2, v2, t2);
        sd = fmaf(v1, v2, sd);
    }
#pragma unroll
    for (int off = 16; off > 0; off >>= 1) {
        sb1 += __shfl_xor_sync(0xffffffff, sb1, off);
        sb2 += __shfl_xor_sync(0xffffffff, sb2, off);
        t1  += __shfl_xor_sync(0xffffffff, t1, off);
        t2  += __shfl_xor_sync(0xffffffff, t2, off);
        sd  += __shfl_xor_sync(0xffffffff, sd, off);
    }
    if (lane == 0) {
        g_sq[p] = sb1;
        g_sq[p + BHALF] = sb2;
        g_row[p] = 0.f;
        g_row[p + BHALF] = 0.f;
        float d2v = fmaxf(t1 + t2 - 2.f * sd, 0.f);
        g_logdiag[p] = -log1pf(d2v);   // log(1/(1+d2))
    }
}

// ---------------------------------------------------------------------------
// K2: main pairwise kernel. CTA = 256x128 super-tile (two stacked 128-blocks
// of rows x one 128-block of cols), upper triangle only (bj >= 2*bip).
// Warp tile 64x64 (4m x 2n grid) -> 33% less LDSM traffic per output than
// the 32x64 variant. Per-warp validity masks handle the sub-diagonal half.
// ---------------------------------------------------------------------------
#define LDS_STRIDE 136   // 128 data + 8 pad bf16 per row (272 B)
#define A_ROWS 256
#define B_ROWS 128
#define A_ELEMS (A_ROWS * LDS_STRIDE)
#define B_ELEMS (B_ROWS * LDS_STRIDE)
#define PAIR_SMEM_BYTES ((A_ELEMS + B_ELEMS) * 2)

__global__ void __launch_bounds__(256, 1) pair_kernel() {
    extern __shared__ __align__(16) __nv_bfloat16 smem_bf[];
    __nv_bfloat16* sA = smem_bf;
    __nv_bfloat16* sB = smem_bf + A_ELEMS;
    __shared__ float s_a[256];   // 1 + |x_i|^2 for tile rows
    __shared__ float s_b[128];   // |y_j|^2 for tile cols

    // map linear tile id -> (bip, bj): for bip in [0,32), bj in [2*bip, 64)
    int rem = blockIdx.x;
    int bip = 0, width = 64;
    while (rem >= width) { rem -= width; bip++; width -= 2; }
    const int bj = 2 * bip + rem;

    const int tid = threadIdx.x;
    const int lane = tid & 31;
    const int wid = tid >> 5;

    // ---- load tiles ----
    const uint4* gA = (const uint4*)(g_Xb + (size_t)bip * 256 * KDIM);
    const uint4* gB = (const uint4*)(g_Xb + (size_t)bj * 128 * KDIM);
#pragma unroll
    for (int it = 0; it < 16; it++) {
        int idx = tid + it * 256;       // 0..4095
        int r = idx >> 4, c = idx & 15;
        *(uint4*)&sA[r * LDS_STRIDE + c * 8] = gA[r * 16 + c];
    }
#pragma unroll
    for (int it = 0; it < 8; it++) {
        int idx = tid + it * 256;       // 0..2047
        int r = idx >> 4, c = idx & 15;
        *(uint4*)&sB[r * LDS_STRIDE + c * 8] = gB[r * 16 + c];
    }
    s_a[tid] = 1.f + g_sq[bip * 256 + tid];
    if (tid < 128) s_b[tid] = g_sq[bj * 128 + tid];
    __syncthreads();

    // ---- warp tiling: 4 (m) x 2 (n); warp tile = 64 x 64 ----
    const int rowbase = (wid & 3) * 64;
    const int colbase = (wid >> 2) * 64;
    // this warp's 128-row-block index and validity vs the triangle
    const int rb = 2 * bip + ((wid & 3) >> 1);
    const bool valid  = (rb <= bj);    // rows belong to upper triangle
    const bool addcol = (rb < bj);     // off-diagonal: also contribute col sums

    float acc[4][8][4];
#pragma unroll
    for (int mi = 0; mi < 4; mi++)
#pragma unroll
        for (int ni = 0; ni < 8; ni++)
#pragma unroll
            for (int r = 0; r < 4; r++) acc[mi][ni][r] = 0.f;

    const int lr = lane & 15;
    const int lc = lane >> 4;
    uint32_t aoff[4], boff[4];
#pragma unroll
    for (int mi = 0; mi < 4; mi++)
        aoff[mi] = smem_u32(&sA[(rowbase + mi * 16 + lr) * LDS_STRIDE + lc * 8]);
#pragma unroll
    for (int nq = 0; nq < 4; nq++)
        boff[nq] = smem_u32(&sB[(colbase + nq * 16 + lr) * LDS_STRIDE + lc * 8]);

#pragma unroll
    for (int ks = 0; ks < 8; ks++) {
        uint32_t a[4][4];
        uint32_t b[8][2];
#pragma unroll
        for (int mi = 0; mi < 4; mi++) {
            asm volatile("ldmatrix.sync.aligned.m8n8.x4.shared.b16 {%0,%1,%2,%3}, [%4];"
                         : "=r"(a[mi][0]), "=r"(a[mi][1]), "=r"(a[mi][2]), "=r"(a[mi][3])
                         : "r"(aoff[mi] + ks * 32));
        }
#pragma unroll
        for (int nq = 0; nq < 4; nq++) {
            uint32_t r0, r1, r2, r3;
            asm volatile("ldmatrix.sync.aligned.m8n8.x4.shared.b16 {%0,%1,%2,%3}, [%4];"
                         : "=r"(r0), "=r"(r1), "=r"(r2), "=r"(r3)
                         : "r"(boff[nq] + ks * 32));
            b[nq * 2 + 0][0] = r0; b[nq * 2 + 1][0] = r1;
            b[nq * 2 + 0][1] = r2; b[nq * 2 + 1][1] = r3;
        }
#pragma unroll
        for (int mi = 0; mi < 4; mi++)
#pragma unroll
            for (int ni = 0; ni < 8; ni++) {
                asm volatile(
                    "mma.sync.aligned.m16n8k16.row.col.f32.bf16.bf16.f32 "
                    "{%0,%1,%2,%3}, {%4,%5,%6,%7}, {%8,%9}, {%0,%1,%2,%3};"
                    : "+f"(acc[mi][ni][0]), "+f"(acc[mi][ni][1]),
                      "+f"(acc[mi][ni][2]), "+f"(acc[mi][ni][3])
                    : "r"(a[mi][0]), "r"(a[mi][1]), "r"(a[mi][2]), "r"(a[mi][3]),
                      "r"(b[ni][0]), "r"(b[ni][1]));
            }
    }

    // ---- epilogue: k = 1 / max(1 + |x|^2 + |y|^2 - 2 x.y, 1) ----
    const int qr = lane >> 2;          // row within 8
    const int qc = (lane & 3) * 2;     // col pair within 8
    float rs[4][2];
#pragma unroll
    for (int mi = 0; mi < 4; mi++) { rs[mi][0] = 0.f; rs[mi][1] = 0.f; }

#pragma unroll
    for (int ni = 0; ni < 8; ni++) {
        float b0 = s_b[colbase + ni * 8 + qc];
        float b1 = s_b[colbase + ni * 8 + qc + 1];
        float cs0 = 0.f, cs1 = 0.f;
#pragma unroll
        for (int mi = 0; mi < 4; mi++) {
            float a0 = s_a[rowbase + mi * 16 + qr];
            float a1 = s_a[rowbase + mi * 16 + qr + 8];
            float k00 = rcp_approx(fmaxf(fmaf(acc[mi][ni][0], -2.f, a0 + b0), 1.f));
            float k01 = rcp_approx(fmaxf(fmaf(acc[mi][ni][1], -2.f, a0 + b1), 1.f));
            float k10 = rcp_approx(fmaxf(fmaf(acc[mi][ni][2], -2.f, a1 + b0), 1.f));
            float k11 = rcp_approx(fmaxf(fmaf(acc[mi][ni][3], -2.f, a1 + b1), 1.f));
            rs[mi][0] += k00 + k01;
            rs[mi][1] += k10 + k11;
            cs0 += k00 + k10;
            cs1 += k01 + k11;
        }
        if (addcol) {
            cs0 += __shfl_xor_sync(0xffffffff, cs0, 4);
            cs1 += __shfl_xor_sync(0xffffffff, cs1, 4);
            cs0 += __shfl_xor_sync(0xffffffff, cs0, 8);
            cs1 += __shfl_xor_sync(0xffffffff, cs1, 8);
            cs0 += __shfl_xor_sync(0xffffffff, cs0, 16);
            cs1 += __shfl_xor_sync(0xffffffff, cs1, 16);
            if (lane < 4) {
                int cg = bj * 128 + colbase + ni * 8 + qc;
                atomicAdd(g_row + cg, cs0);
                atomicAdd(g_row + cg + 1, cs1);
            }
        }
    }

    if (valid) {
#pragma unroll
        for (int mi = 0; mi < 4; mi++) {
#pragma unroll
            for (int h = 0; h < 2; h++) {
                rs[mi][h] += __shfl_xor_sync(0xffffffff, rs[mi][h], 1);
                rs[mi][h] += __shfl_xor_sync(0xffffffff, rs[mi][h], 2);
            }
            if ((lane & 3) == 0) {
                int r0 = bip * 256 + rowbase + mi * 16 + qr;
                atomicAdd(g_row + r0, rs[mi][0]);
                atomicAdd(g_row + r0 + 8, rs[mi][1]);
            }
        }
    }
}

// ---------------------------------------------------------------------------
// K3: parallel finalize. 16 CTAs x 512 threads; partial sums -> atomics;
// last block combines and writes the scalar.
// ---------------------------------------------------------------------------
__global__ void finalize_kernel(float* out) {
    const int tid = threadIdx.x;
    const int b = blockIdx.x;
    int row = b * 512 + tid;                 // 16*512 = 8192
    float an = __logf(g_row[row] - 1.0f);
    float ap = (tid < 256) ? g_logdiag[b * 256 + tid] : 0.f;
#pragma unroll
    for (int off = 16; off > 0; off >>= 1) {
        an += __shfl_xor_sync(0xffffffff, an, off);
        ap += __shfl_xor_sync(0xffffffff, ap, off);
    }
    __shared__ float sn[16], sp[16];
    int wid = tid >> 5, lane = tid & 31;
    if (lane == 0) { sn[wid] = an; sp[wid] = ap; }
    __syncthreads();
    if (tid == 0) {
        float tn = 0.f, tp = 0.f;
#pragma unroll
        for (int i = 0; i < 16; i++) { tn += sn[i]; tp += sp[i]; }
        atomicAdd(&g_part[0], tn);
        atomicAdd(&g_part[1], tp);
        __threadfence();
        unsigned int done = atomicAdd(&g_cnt, 1u);
        if (done == 15u) {
            float neg = *((volatile float*)&g_part[0]) / (2.0f * (float)BHALF);
            float pos = *((volatile float*)&g_part[1]) / (float)BHALF;
            out[0] = neg - pos;   // -(pos - neg)
        }
    }
}

// ---------------------------------------------------------------------------
extern "C" void kernel_launch(void* const* d_in, const int* in_sizes, int n_in,
                              void* d_out, int out_size) {
    const float* feat = (const float*)d_in[0];
    float* out = (float*)d_out;

    cudaFuncSetAttribute(pair_kernel,
                         cudaFuncAttributeMaxDynamicSharedMemorySize,
                         PAIR_SMEM_BYTES);

    prep_kernel<<<BHALF / 8, 256>>>(feat);
    pair_kernel<<<NTILES2, 256, PAIR_SMEM_BYTES>>>();
    finalize_kernel<<<16, 512>>>(out);
}

// round 6
// speedup vs baseline: 1.6285x; 1.2303x over previous
#include <cuda_runtime.h>
#include <cuda_bf16.h>
#include <cstdint>

#define NROWS 8192
#define BHALF 4096
#define KDIM  128
#define NBLK  64
#define NTILES 2080          // upper-triangle 128x128 tiles
#define PCTAS  296           // persistent CTAs (2 per SM)

// Scratch (device globals — no allocation allowed in kernel_launch)
__device__ __nv_bfloat16 g_Xb[NROWS * KDIM];   // bf16 copy of features
__device__ float g_sq[NROWS];                  // |x|^2 from bf16-rounded values
__device__ float g_row[NROWS];                 // full row sums of 8192x8192 kernel matrix
__device__ float g_logdiag[BHALF];             // log k12(i,i), fp32 path
__device__ float g_part[2];                    // partial sums for finalize
__device__ unsigned int g_cnt;                 // finalize block counter

static __device__ __forceinline__ uint32_t smem_u32(const void* p) {
    return (uint32_t)__cvta_generic_to_shared(p);
}

static __device__ __forceinline__ float rcp_approx(float x) {
    float r;
    asm("rcp.approx.ftz.f32 %0, %1;" : "=f"(r) : "f"(x));
    return r;
}

static __device__ __forceinline__ void cp_async16(uint32_t dst, const void* src) {
    asm volatile("cp.async.cg.shared.global [%0], [%1], 16;"
                 :: "r"(dst), "l"(src));
}
static __device__ __forceinline__ void cp_commit() {
    asm volatile("cp.async.commit_group;" ::: "memory");
}

// ---------------------------------------------------------------------------
// K1: fused prep + diag. One warp per pair (i, i+4096).
// ---------------------------------------------------------------------------
__global__ void prep_kernel(const float* __restrict__ feat) {
    int w = threadIdx.x >> 5;
    int lane = threadIdx.x & 31;
    int p = blockIdx.x * 8 + w;           // 0..4095
    if (blockIdx.x == 0 && threadIdx.x == 0) {
        g_part[0] = 0.f; g_part[1] = 0.f; g_cnt = 0u;
    }
    if (p >= BHALF) return;
    const float* f1 = feat + (size_t)p * KDIM;
    const float* f2 = feat + (size_t)(p + BHALF) * KDIM;
    __nv_bfloat16* d1 = g_Xb + (size_t)p * KDIM;
    __nv_bfloat16* d2 = g_Xb + (size_t)(p + BHALF) * KDIM;
    float sb1 = 0.f, sb2 = 0.f;
    float t1 = 0.f, t2 = 0.f, sd = 0.f;
#pragma unroll
    for (int c = 0; c < 4; c++) {
        float v1 = f1[c * 32 + lane];
        float v2 = f2[c * 32 + lane];
        __nv_bfloat16 h1 = __float2bfloat16(v1);
        __nv_bfloat16 h2 = __float2bfloat16(v2);
        d1[c * 32 + lane] = h1;
        d2[c * 32 + lane] = h2;
        float b1 = __bfloat162float(h1);
        float b2 = __bfloat162float(h2);
        sb1 = fmaf(b1, b1, sb1);
        sb2 = fmaf(b2, b2, sb2);
        t1 = fmaf(v1, v1, t1);
        t2 = fmaf(v2, v2, t2);
        sd = fmaf(v1, v2, sd);
    }
#pragma unroll
    for (int off = 16; off > 0; off >>= 1) {
        sb1 += __shfl_xor_sync(0xffffffff, sb1, off);
        sb2 += __shfl_xor_sync(0xffffffff, sb2, off);
        t1  += __shfl_xor_sync(0xffffffff, t1, off);
        t2  += __shfl_xor_sync(0xffffffff, t2, off);
        sd  += __shfl_xor_sync(0xffffffff, sd, off);
    }
    if (lane == 0) {
        g_sq[p] = sb1;
        g_sq[p + BHALF] = sb2;
        g_row[p] = 0.f;
        g_row[p + BHALF] = 0.f;
        float d2v = fmaxf(t1 + t2 - 2.f * sd, 0.f);
        g_logdiag[p] = -log1pf(d2v);
    }
}

// ---------------------------------------------------------------------------
// K2: persistent, software-pipelined pairwise kernel.
// 296 CTAs; each handles 7-8 consecutive upper-triangle tiles in bi-major
// order. A tile (bi block) resident in smem across the chunk; B double-
// buffered via cp.async prefetch. mma.sync m16n8k16 bf16, fused Cauchy
// epilogue with row + column sums.
// ---------------------------------------------------------------------------
#define LDS_STRIDE 136   // bf16 per smem row: 128 data + 8 pad (272 B)
#define TILE_BYTES (128 * LDS_STRIDE * 2)      // 34816
#define PAIR_SMEM_BYTES (3 * TILE_BYTES)       // A + 2x B = 104448

__global__ void __launch_bounds__(256, 2) pair_kernel() {
    extern __shared__ __align__(16) char dynsm[];
    char* sAp = dynsm;
    char* sBp[2] = { dynsm + TILE_BYTES, dynsm + 2 * TILE_BYTES };
    const uint32_t abase = smem_u32(sAp);
    const uint32_t bbase0 = abase + TILE_BYTES;
    __shared__ float s_a[128];        // |x|^2 for A rows (raw)
    __shared__ float s_bb[2][128];    // |y|^2 for B rows (raw), per buffer

    const int tid = threadIdx.x;
    const int lane = tid & 31;
    const int wid = tid >> 5;

    // ---- chunk of tiles for this CTA ----
    const int b = blockIdx.x;
    const int start = b * 7 + (b < 8 ? b : 8);
    const int cnt = 7 + (b < 8 ? 1 : 0);
    // map start -> (bi, bj), bi-major: for bi: bj in [bi, 64)
    int bi = 0, rem = start;
    while (rem >= NBLK - bi) { rem -= NBLK - bi; bi++; }
    int bj = bi + rem;

    // ---- helpers (lambdas) ----
    auto issue_B = [&](int blk, int buf) {
        const char* g = (const char*)(g_Xb + (size_t)blk * 128 * KDIM);
        uint32_t sb = bbase0 + buf * TILE_BYTES;
#pragma unroll
        for (int it = 0; it < 8; it++) {
            int idx = tid + it * 256;
            int r = idx >> 4, c = idx & 15;
            cp_async16(sb + r * 272 + c * 16, g + r * 256 + c * 16);
        }
        if (tid < 32)
            cp_async16(smem_u32(&s_bb[buf][0]) + tid * 16,
                       (const char*)(g_sq + blk * 128) + tid * 16);
    };
    auto issue_A = [&](int blk) {
        const char* g = (const char*)(g_Xb + (size_t)blk * 128 * KDIM);
#pragma unroll
        for (int it = 0; it < 8; it++) {
            int idx = tid + it * 256;
            int r = idx >> 4, c = idx & 15;
            cp_async16(abase + r * 272 + c * 16, g + r * 256 + c * 16);
        }
        if (tid < 32)
            cp_async16(smem_u32(&s_a[0]) + tid * 16,
                       (const char*)(g_sq + blk * 128) + tid * 16);
    };

    // ---- warp tiling constants: 4 (m) x 2 (n); warp tile = 32 x 64 ----
    const int rowbase = (wid & 3) * 32;
    const int colbase = (wid >> 2) * 64;
    const int lr = lane & 15;
    const int lc = lane >> 4;
    uint32_t aoff[2];
    uint32_t brel[4];
#pragma unroll
    for (int mi = 0; mi < 2; mi++)
        aoff[mi] = abase + (uint32_t)((rowbase + mi * 16 + lr) * 272 + lc * 16);
#pragma unroll
    for (int nq = 0; nq < 4; nq++)
        brel[nq] = (uint32_t)((colbase + nq * 16 + lr) * 272 + lc * 16);

    const int qr = lane >> 2;
    const int qc = (lane & 3) * 2;

    // ---- prime the pipeline: A(bi) + B(bj) into buf 0 ----
    issue_A(bi);
    issue_B(bj, 0);
    cp_commit();

    for (int i = 0; i < cnt; i++) {
        const int cur = i & 1;
        // next tile coords
        int nbi = bi, nbj = bj + 1;
        if (nbj == NBLK) { nbi++; nbj = nbi; }
        const bool have_next = (i + 1 < cnt);
        const bool same_bi = have_next && (nbi == bi);

        // prefetch next B while current tile computes (same A block only)
        if (same_bi) {
            issue_B(nbj, cur ^ 1);
            cp_commit();
            asm volatile("cp.async.wait_group 1;" ::: "memory");
        } else {
            asm volatile("cp.async.wait_group 0;" ::: "memory");
        }
        __syncthreads();

        const uint32_t bb = bbase0 + cur * TILE_BYTES;
        const float* s_b = s_bb[cur];

        // ---- mma over K=128 (8 steps of 16) ----
        float acc[2][8][4];
#pragma unroll
        for (int mi = 0; mi < 2; mi++)
#pragma unroll
            for (int ni = 0; ni < 8; ni++)
#pragma unroll
                for (int r = 0; r < 4; r++) acc[mi][ni][r] = 0.f;

#pragma unroll
        for (int ks = 0; ks < 8; ks++) {
            uint32_t a[2][4];
            uint32_t bfr[8][2];
#pragma unroll
            for (int mi = 0; mi < 2; mi++) {
                asm volatile("ldmatrix.sync.aligned.m8n8.x4.shared.b16 {%0,%1,%2,%3}, [%4];"
                             : "=r"(a[mi][0]), "=r"(a[mi][1]), "=r"(a[mi][2]), "=r"(a[mi][3])
                             : "r"(aoff[mi] + ks * 32));
            }
#pragma unroll
            for (int nq = 0; nq < 4; nq++) {
                uint32_t r0, r1, r2, r3;
                asm volatile("ldmatrix.sync.aligned.m8n8.x4.shared.b16 {%0,%1,%2,%3}, [%4];"
                             : "=r"(r0), "=r"(r1), "=r"(r2), "=r"(r3)
                             : "r"(bb + brel[nq] + ks * 32));
                bfr[nq * 2 + 0][0] = r0; bfr[nq * 2 + 1][0] = r1;
                bfr[nq * 2 + 0][1] = r2; bfr[nq * 2 + 1][1] = r3;
            }
#pragma unroll
            for (int mi = 0; mi < 2; mi++)
#pragma unroll
                for (int ni = 0; ni < 8; ni++) {
                    asm volatile(
                        "mma.sync.aligned.m16n8k16.row.col.f32.bf16.bf16.f32 "
                        "{%0,%1,%2,%3}, {%4,%5,%6,%7}, {%8,%9}, {%0,%1,%2,%3};"
                        : "+f"(acc[mi][ni][0]), "+f"(acc[mi][ni][1]),
                          "+f"(acc[mi][ni][2]), "+f"(acc[mi][ni][3])
                        : "r"(a[mi][0]), "r"(a[mi][1]), "r"(a[mi][2]), "r"(a[mi][3]),
                          "r"(bfr[ni][0]), "r"(bfr[ni][1]));
                }
        }

        // ---- epilogue: k = 1 / max(1 + |x|^2 + |y|^2 - 2 x.y, 1) ----
        const bool offdiag = (bi != bj);
        float rs[2][2] = {{0.f, 0.f}, {0.f, 0.f}};
#pragma unroll
        for (int ni = 0; ni < 8; ni++) {
            float b0 = s_b[colbase + ni * 8 + qc];
            float b1 = s_b[colbase + ni * 8 + qc + 1];
            float cs0 = 0.f, cs1 = 0.f;
#pragma unroll
            for (int mi = 0; mi < 2; mi++) {
                float a0 = 1.f + s_a[rowbase + mi * 16 + qr];
                float a1 = 1.f + s_a[rowbase + mi * 16 + qr + 8];
                float k00 = rcp_approx(fmaxf(fmaf(acc[mi][ni][0], -2.f, a0 + b0), 1.f));
                float k01 = rcp_approx(fmaxf(fmaf(acc[mi][ni][1], -2.f, a0 + b1), 1.f));
                float k10 = rcp_approx(fmaxf(fmaf(acc[mi][ni][2], -2.f, a1 + b0), 1.f));
                float k11 = rcp_approx(fmaxf(fmaf(acc[mi][ni][3], -2.f, a1 + b1), 1.f));
                rs[mi][0] += k00 + k01;
                rs[mi][1] += k10 + k11;
                cs0 += k00 + k10;
                cs1 += k01 + k11;
            }
            if (offdiag) {
                cs0 += __shfl_xor_sync(0xffffffff, cs0, 4);
                cs1 += __shfl_xor_sync(0xffffffff, cs1, 4);
                cs0 += __shfl_xor_sync(0xffffffff, cs0, 8);
                cs1 += __shfl_xor_sync(0xffffffff, cs1, 8);
                cs0 += __shfl_xor_sync(0xffffffff, cs0, 16);
                cs1 += __shfl_xor_sync(0xffffffff, cs1, 16);
                if (lane < 4) {
                    int cg = bj * 128 + colbase + ni * 8 + qc;
                    atomicAdd(g_row + cg, cs0);
                    atomicAdd(g_row + cg + 1, cs1);
                }
            }
        }
#pragma unroll
        for (int mi = 0; mi < 2; mi++) {
#pragma unroll
            for (int h = 0; h < 2; h++) {
                rs[mi][h] += __shfl_xor_sync(0xffffffff, rs[mi][h], 1);
                rs[mi][h] += __shfl_xor_sync(0xffffffff, rs[mi][h], 2);
            }
            if ((lane & 3) == 0) {
                int r0 = bi * 128 + rowbase + mi * 16 + qr;
                atomicAdd(g_row + r0, rs[mi][0]);
                atomicAdd(g_row + r0 + 8, rs[mi][1]);
            }
        }

        // bi crossing: reload A (and B for next tile) after everyone is done
        if (have_next && !same_bi) {
            __syncthreads();          // protect s_a / sA from overwrite
            issue_A(nbi);
            issue_B(nbj, cur ^ 1);
            cp_commit();
        }
        bi = nbi; bj = nbj;
    }
}

// ---------------------------------------------------------------------------
// K3: parallel finalize.
// ---------------------------------------------------------------------------
__global__ void finalize_kernel(float* out) {
    const int tid = threadIdx.x;
    const int b = blockIdx.x;
    int row = b * 512 + tid;                 // 16*512 = 8192
    float an = __logf(g_row[row] - 1.0f);
    float ap = (tid < 256) ? g_logdiag[b * 256 + tid] : 0.f;
#pragma unroll
    for (int off = 16; off > 0; off >>= 1) {
        an += __shfl_xor_sync(0xffffffff, an, off);
        ap += __shfl_xor_sync(0xffffffff, ap, off);
    }
    __shared__ float sn[16], sp[16];
    int wid = tid >> 5, lane = tid & 31;
    if (lane == 0) { sn[wid] = an; sp[wid] = ap; }
    __syncthreads();
    if (tid == 0) {
        float tn = 0.f, tp = 0.f;
#pragma unroll
        for (int i = 0; i < 16; i++) { tn += sn[i]; tp += sp[i]; }
        atomicAdd(&g_part[0], tn);
        atomicAdd(&g_part[1], tp);
        __threadfence();
        unsigned int done = atomicAdd(&g_cnt, 1u);
        if (done == 15u) {
            float neg = *((volatile float*)&g_part[0]) / (2.0f * (float)BHALF);
            float pos = *((volatile float*)&g_part[1]) / (float)BHALF;
            out[0] = neg - pos;   // -(pos - neg)
        }
    }
}

// ---------------------------------------------------------------------------
extern "C" void kernel_launch(void* const* d_in, const int* in_sizes, int n_in,
                              void* d_out, int out_size) {
    const float* feat = (const float*)d_in[0];
    float* out = (float*)d_out;

    cudaFuncSetAttribute(pair_kernel,
                         cudaFuncAttributeMaxDynamicSharedMemorySize,
                         PAIR_SMEM_BYTES);

    prep_kernel<<<BHALF / 8, 256>>>(feat);
    pair_kernel<<<PCTAS, 256, PAIR_SMEM_BYTES>>>();
    finalize_kernel<<<16, 512>>>(out);
}

// round 7
// speedup vs baseline: 1.6952x; 1.0409x over previous
#include <cuda_runtime.h>
#include <cuda_bf16.h>
#include <cstdint>

#define NROWS 8192
#define BHALF 4096
#define KDIM  128
#define NBLK  64
#define PCTAS  296           // persistent CTAs (2 per SM)

typedef unsigned long long ull;

// Scratch (device globals — no allocation allowed in kernel_launch)
__device__ __nv_bfloat16 g_Xb[NROWS * KDIM];   // bf16 copy of features
__device__ float g_sq[NROWS];                  // |x|^2 from bf16-rounded values
__device__ float g_row[NROWS];                 // full row sums of 8192x8192 kernel matrix
__device__ float g_logdiag[BHALF];             // log k12(i,i), fp32 path
__device__ float g_part[2];                    // partial sums for finalize
__device__ unsigned int g_cnt;                 // finalize block counter

static __device__ __forceinline__ uint32_t smem_u32(const void* p) {
    return (uint32_t)__cvta_generic_to_shared(p);
}

static __device__ __forceinline__ float rcp_approx(float x) {
    float r;
    asm("rcp.approx.ftz.f32 %0, %1;" : "=f"(r) : "f"(x));
    return r;
}

static __device__ __forceinline__ void cp_async16(uint32_t dst, const void* src) {
    asm volatile("cp.async.cg.shared.global [%0], [%1], 16;"
                 :: "r"(dst), "l"(src));
}
static __device__ __forceinline__ void cp_commit() {
    asm volatile("cp.async.commit_group;" ::: "memory");
}

// packed fp32 pair helpers (Blackwell FFMA2 path)
#define PACK2(o, lo, hi)  asm("mov.b64 %0, {%1, %2};" : "=l"(o) : "f"(lo), "f"(hi))
#define UNPACK2(lo, hi, i) asm("mov.b64 {%0, %1}, %2;" : "=f"(lo), "=f"(hi) : "l"(i))
#define ADDX2(o, a, b)     asm("add.rn.f32x2 %0, %1, %2;" : "=l"(o) : "l"(a), "l"(b))
#define FMAX2(o, a, b, c)  asm("fma.rn.f32x2 %0, %1, %2, %3;" : "=l"(o) : "l"(a), "l"(b), "l"(c))

// ---------------------------------------------------------------------------
// K1: fused prep + diag. One warp per pair (i, i+4096). float4 row loads.
// ---------------------------------------------------------------------------
__global__ void prep_kernel(const float* __restrict__ feat) {
    int w = threadIdx.x >> 5;
    int lane = threadIdx.x & 31;
    int p = blockIdx.x * 8 + w;           // 0..4095
    if (blockIdx.x == 0 && threadIdx.x == 0) {
        g_part[0] = 0.f; g_part[1] = 0.f; g_cnt = 0u;
    }
    if (p >= BHALF) return;
    float4 v1 = ((const float4*)(feat + (size_t)p * KDIM))[lane];
    float4 v2 = ((const float4*)(feat + (size_t)(p + BHALF) * KDIM))[lane];

    __nv_bfloat162 h1a = __floats2bfloat162_rn(v1.x, v1.y);
    __nv_bfloat162 h1b = __floats2bfloat162_rn(v1.z, v1.w);
    __nv_bfloat162 h2a = __floats2bfloat162_rn(v2.x, v2.y);
    __nv_bfloat162 h2b = __floats2bfloat162_rn(v2.z, v2.w);
    uint2 s1u, s2u;
    s1u.x = *(uint32_t*)&h1a; s1u.y = *(uint32_t*)&h1b;
    s2u.x = *(uint32_t*)&h2a; s2u.y = *(uint32_t*)&h2b;
    ((uint2*)(g_Xb + (size_t)p * KDIM))[lane] = s1u;
    ((uint2*)(g_Xb + (size_t)(p + BHALF) * KDIM))[lane] = s2u;

    float2 r1a = __bfloat1622float2(h1a), r1b = __bfloat1622float2(h1b);
    float2 r2a = __bfloat1622float2(h2a), r2b = __bfloat1622float2(h2b);
    float sb1 = r1a.x * r1a.x + r1a.y * r1a.y + r1b.x * r1b.x + r1b.y * r1b.y;
    float sb2 = r2a.x * r2a.x + r2a.y * r2a.y + r2b.x * r2b.x + r2b.y * r2b.y;
    float t1 = v1.x * v1.x + v1.y * v1.y + v1.z * v1.z + v1.w * v1.w;
    float t2 = v2.x * v2.x + v2.y * v2.y + v2.z * v2.z + v2.w * v2.w;
    float sd = v1.x * v2.x + v1.y * v2.y + v1.z * v2.z + v1.w * v2.w;

#pragma unroll
    for (int off = 16; off > 0; off >>= 1) {
        sb1 += __shfl_xor_sync(0xffffffff, sb1, off);
        sb2 += __shfl_xor_sync(0xffffffff, sb2, off);
        t1  += __shfl_xor_sync(0xffffffff, t1, off);
        t2  += __shfl_xor_sync(0xffffffff, t2, off);
        sd  += __shfl_xor_sync(0xffffffff, sd, off);
    }
    if (lane == 0) {
        g_sq[p] = sb1;
        g_sq[p + BHALF] = sb2;
        g_row[p] = 0.f;
        g_row[p + BHALF] = 0.f;
        float d2v = fmaxf(t1 + t2 - 2.f * sd, 0.f);
        g_logdiag[p] = -log1pf(d2v);
    }
}

// ---------------------------------------------------------------------------
// K2: persistent, software-pipelined pairwise kernel (race-fixed).
// 296 CTAs x 7-8 upper-triangle tiles, bi-major; A resident per chunk,
// B double-buffered via cp.async. All buffer writes are issued only after
// the loop-top __syncthreads(), so no warp can still be reading them.
// ---------------------------------------------------------------------------
#define LDS_STRIDE 136   // bf16 per smem row: 128 data + 8 pad (272 B)
#define TILE_BYTES (128 * LDS_STRIDE * 2)      // 34816
#define PAIR_SMEM_BYTES (3 * TILE_BYTES)       // A + 2x B = 104448

__global__ void __launch_bounds__(256, 2) pair_kernel() {
    extern __shared__ __align__(16) char dynsm[];
    const uint32_t abase = smem_u32(dynsm);
    const uint32_t bbase0 = abase + TILE_BYTES;
    __shared__ float s_a[128];        // |x|^2 for A rows (raw)
    __shared__ float s_bb[2][128];    // |y|^2 for B rows (raw), per buffer

    const int tid = threadIdx.x;
    const int lane = tid & 31;
    const int wid = tid >> 5;

    // ---- chunk of tiles for this CTA ----
    const int b = blockIdx.x;
    const int start = b * 7 + (b < 8 ? b : 8);
    const int cnt = 7 + (b < 8 ? 1 : 0);
    int bi = 0, rem = start;
    while (rem >= NBLK - bi) { rem -= NBLK - bi; bi++; }
    int bj = bi + rem;

    auto issue_B = [&](int blk, int buf) {
        const char* g = (const char*)(g_Xb + (size_t)blk * 128 * KDIM);
        uint32_t sb = bbase0 + buf * TILE_BYTES;
#pragma unroll
        for (int it = 0; it < 8; it++) {
            int idx = tid + it * 256;
            int r = idx >> 4, c = idx & 15;
            cp_async16(sb + r * 272 + c * 16, g + r * 256 + c * 16);
        }
        if (tid < 32)
            cp_async16(smem_u32(&s_bb[buf][0]) + tid * 16,
                       (const char*)(g_sq + blk * 128) + tid * 16);
    };
    auto issue_A = [&](int blk) {
        const char* g = (const char*)(g_Xb + (size_t)blk * 128 * KDIM);
#pragma unroll
        for (int it = 0; it < 8; it++) {
            int idx = tid + it * 256;
            int r = idx >> 4, c = idx & 15;
            cp_async16(abase + r * 272 + c * 16, g + r * 256 + c * 16);
        }
        if (tid < 32)
            cp_async16(smem_u32(&s_a[0]) + tid * 16,
                       (const char*)(g_sq + blk * 128) + tid * 16);
    };

    // ---- warp tiling constants: 4 (m) x 2 (n); warp tile = 32 x 64 ----
    const int rowbase = (wid & 3) * 32;
    const int colbase = (wid >> 2) * 64;
    const int lr = lane & 15;
    const int lc = lane >> 4;
    uint32_t aoff[2];
    uint32_t brel[4];
#pragma unroll
    for (int mi = 0; mi < 2; mi++)
        aoff[mi] = abase + (uint32_t)((rowbase + mi * 16 + lr) * 272 + lc * 16);
#pragma unroll
    for (int nq = 0; nq < 4; nq++)
        brel[nq] = (uint32_t)((colbase + nq * 16 + lr) * 272 + lc * 16);

    const int qr = lane >> 2;
    const int qc = (lane & 3) * 2;

    // ---- prime: A(bi) + B(bj) into buf 0, one commit group ----
    issue_A(bi);
    issue_B(bj, 0);
    cp_commit();
    bool need_cur = false;   // current tile's buffers already issued?

    for (int i = 0; i < cnt; i++) {
        const int cur = i & 1;
        int nbi = bi, nbj = bj + 1;
        if (nbj == NBLK) { nbi++; nbj = nbi; }
        const bool have_next = (i + 1 < cnt);
        const bool same_bi = have_next && (nbi == bi);

        // All issuance happens after this barrier: no warp is still reading
        // any smem buffer from the previous iteration.
        if (i > 0) __syncthreads();
        if (need_cur) {            // bi crossing happened: load A(bi)+B(bj,cur)
            issue_A(bi);
            issue_B(bj, cur);
            cp_commit();
        }
        if (same_bi) {             // prefetch next B while this tile computes
            issue_B(nbj, cur ^ 1);
            cp_commit();
            asm volatile("cp.async.wait_group 1;" ::: "memory");
        } else {
            asm volatile("cp.async.wait_group 0;" ::: "memory");
        }
        __syncthreads();
        need_cur = have_next && (nbi != bi);

        const uint32_t bb = bbase0 + cur * TILE_BYTES;
        const float* s_b = s_bb[cur];

        // ---- mma over K=128 (8 steps of 16) ----
        float acc[2][8][4];
#pragma unroll
        for (int mi = 0; mi < 2; mi++)
#pragma unroll
            for (int ni = 0; ni < 8; ni++)
#pragma unroll
                for (int r = 0; r < 4; r++) acc[mi][ni][r] = 0.f;

#pragma unroll
        for (int ks = 0; ks < 8; ks++) {
            uint32_t a[2][4];
            uint32_t bfr[8][2];
#pragma unroll
            for (int mi = 0; mi < 2; mi++) {
                asm volatile("ldmatrix.sync.aligned.m8n8.x4.shared.b16 {%0,%1,%2,%3}, [%4];"
                             : "=r"(a[mi][0]), "=r"(a[mi][1]), "=r"(a[mi][2]), "=r"(a[mi][3])
                             : "r"(aoff[mi] + ks * 32));
            }
#pragma unroll
            for (int nq = 0; nq < 4; nq++) {
                uint32_t r0, r1, r2, r3;
                asm volatile("ldmatrix.sync.aligned.m8n8.x4.shared.b16 {%0,%1,%2,%3}, [%4];"
                             : "=r"(r0), "=r"(r1), "=r"(r2), "=r"(r3)
                             : "r"(bb + brel[nq] + ks * 32));
                bfr[nq * 2 + 0][0] = r0; bfr[nq * 2 + 1][0] = r1;
                bfr[nq * 2 + 0][1] = r2; bfr[nq * 2 + 1][1] = r3;
            }
#pragma unroll
            for (int mi = 0; mi < 2; mi++)
#pragma unroll
                for (int ni = 0; ni < 8; ni++) {
                    asm volatile(
                        "mma.sync.aligned.m16n8k16.row.col.f32.bf16.bf16.f32 "
                        "{%0,%1,%2,%3}, {%4,%5,%6,%7}, {%8,%9}, {%0,%1,%2,%3};"
                        : "+f"(acc[mi][ni][0]), "+f"(acc[mi][ni][1]),
                          "+f"(acc[mi][ni][2]), "+f"(acc[mi][ni][3])
                        : "r"(a[mi][0]), "r"(a[mi][1]), "r"(a[mi][2]), "r"(a[mi][3]),
                          "r"(bfr[ni][0]), "r"(bfr[ni][1]));
                }
        }

        // ---- epilogue (packed f32x2): k = 1/(1 + |x|^2 + |y|^2 - 2 x.y) ----
        const bool offdiag = (bi != bj);
        ull M2, ZER;
        PACK2(M2, -2.f, -2.f);
        PACK2(ZER, 0.f, 0.f);
        ull apk[2][2];
#pragma unroll
        for (int mi = 0; mi < 2; mi++) {
            float a0 = 1.f + s_a[rowbase + mi * 16 + qr];
            float a1 = 1.f + s_a[rowbase + mi * 16 + qr + 8];
            PACK2(apk[mi][0], a0, a0);
            PACK2(apk[mi][1], a1, a1);
        }
        ull rsp[2][2] = {{ZER, ZER}, {ZER, ZER}};

#pragma unroll
        for (int ni = 0; ni < 8; ni++) {
            float2 bp = *(const float2*)&s_b[colbase + ni * 8 + qc];
            ull bpk; PACK2(bpk, bp.x, bp.y);
            ull csp = ZER;
#pragma unroll
            for (int mi = 0; mi < 2; mi++) {
                ull t0, t1;
                ADDX2(t0, apk[mi][0], bpk);
                ADDX2(t1, apk[mi][1], bpk);
                ull a01, a23;
                PACK2(a01, acc[mi][ni][0], acc[mi][ni][1]);
                PACK2(a23, acc[mi][ni][2], acc[mi][ni][3]);
                ull d0, d1;
                FMAX2(d0, a01, M2, t0);
                FMAX2(d1, a23, M2, t1);
                float f00, f01, f10, f11;
                UNPACK2(f00, f01, d0);
                UNPACK2(f10, f11, d1);
                ull k01, k23;
                PACK2(k01, rcp_approx(f00), rcp_approx(f01));
                PACK2(k23, rcp_approx(f10), rcp_approx(f11));
                ADDX2(rsp[mi][0], rsp[mi][0], k01);
                ADDX2(rsp[mi][1], rsp[mi][1], k23);
                ADDX2(csp, csp, k01);
                ADDX2(csp, csp, k23);
            }
            if (offdiag) {
                float cs0, cs1;
                UNPACK2(cs0, cs1, csp);
                cs0 += __shfl_xor_sync(0xffffffff, cs0, 4);
                cs1 += __shfl_xor_sync(0xffffffff, cs1, 4);
                cs0 += __shfl_xor_sync(0xffffffff, cs0, 8);
                cs1 += __shfl_xor_sync(0xffffffff, cs1, 8);
                cs0 += __shfl_xor_sync(0xffffffff, cs0, 16);
                cs1 += __shfl_xor_sync(0xffffffff, cs1, 16);
                if (lane < 4) {
                    int cg = bj * 128 + colbase + ni * 8 + qc;
                    atomicAdd(g_row + cg, cs0);
                    atomicAdd(g_row + cg + 1, cs1);
                }
            }
        }
#pragma unroll
        for (int mi = 0; mi < 2; mi++) {
            float rs0, rs1, x, y;
            UNPACK2(x, y, rsp[mi][0]); rs0 = x + y;
            UNPACK2(x, y, rsp[mi][1]); rs1 = x + y;
            rs0 += __shfl_xor_sync(0xffffffff, rs0, 1);
            rs1 += __shfl_xor_sync(0xffffffff, rs1, 1);
            rs0 += __shfl_xor_sync(0xffffffff, rs0, 2);
            rs1 += __shfl_xor_sync(0xffffffff, rs1, 2);
            if ((lane & 3) == 0) {
                int r0 = bi * 128 + rowbase + mi * 16 + qr;
                atomicAdd(g_row + r0, rs0);
                atomicAdd(g_row + r0 + 8, rs1);
            }
        }

        bi = nbi; bj = nbj;
    }
}

// ---------------------------------------------------------------------------
// K3: parallel finalize.
// ---------------------------------------------------------------------------
__global__ void finalize_kernel(float* out) {
    const int tid = threadIdx.x;
    const int b = blockIdx.x;
    int row = b * 512 + tid;                 // 16*512 = 8192
    float an = __logf(g_row[row] - 1.0f);
    float ap = (tid < 256) ? g_logdiag[b * 256 + tid] : 0.f;
#pragma unroll
    for (int off = 16; off > 0; off >>= 1) {
        an += __shfl_xor_sync(0xffffffff, an, off);
        ap += __shfl_xor_sync(0xffffffff, ap, off);
    }
    __shared__ float sn[16], sp[16];
    int wid = tid >> 5, lane = tid & 31;
    if (lane == 0) { sn[wid] = an; sp[wid] = ap; }
    __syncthreads();
    if (tid == 0) {
        float tn = 0.f, tp = 0.f;
#pragma unroll
        for (int i = 0; i < 16; i++) { tn += sn[i]; tp += sp[i]; }
        atomicAdd(&g_part[0], tn);
        atomicAdd(&g_part[1], tp);
        __threadfence();
        unsigned int done = atomicAdd(&g_cnt, 1u);
        if (done == 15u) {
            float neg = *((volatile float*)&g_part[0]) / (2.0f * (float)BHALF);
            float pos = *((volatile float*)&g_part[1]) / (float)BHALF;
            out[0] = neg - pos;   // -(pos - neg)
        }
    }
}

// ---------------------------------------------------------------------------
extern "C" void kernel_launch(void* const* d_in, const int* in_sizes, int n_in,
                              void* d_out, int out_size) {
    const float* feat = (const float*)d_in[0];
    float* out = (float*)d_out;

    cudaFuncSetAttribute(pair_kernel,
                         cudaFuncAttributeMaxDynamicSharedMemorySize,
                         PAIR_SMEM_BYTES);

    prep_kernel<<<BHALF / 8, 256>>>(feat);
    pair_kernel<<<PCTAS, 256, PAIR_SMEM_BYTES>>>();
    finalize_kernel<<<16, 512>>>(out);
}

// round 8
// speedup vs baseline: 1.7064x; 1.0066x over previous
#include <cuda_runtime.h>
#include <cuda_bf16.h>
#include <cuda_fp16.h>
#include <cstdint>

#define NROWS 8192
#define BHALF 4096
#define KDIM  128
#define NBLK  64
#define PCTAS  296           // persistent CTAs (2 per SM)

typedef unsigned long long ull;

// Scratch (device globals — no allocation allowed in kernel_launch)
__device__ uint8_t g_X8[NROWS * KDIM];         // e4m3 copy of features
__device__ float g_sq[NROWS];                  // |x|^2 from fp8-rounded values
__device__ float g_row[NROWS];                 // full row sums of 8192x8192 kernel matrix
__device__ float g_logdiag[BHALF];             // log k12(i,i), fp32 path
__device__ float g_part[2];                    // partial sums for finalize
__device__ unsigned int g_cnt;                 // finalize block counter

static __device__ __forceinline__ uint32_t smem_u32(const void* p) {
    return (uint32_t)__cvta_generic_to_shared(p);
}

static __device__ __forceinline__ float rcp_approx(float x) {
    float r;
    asm("rcp.approx.ftz.f32 %0, %1;" : "=f"(r) : "f"(x));
    return r;
}

static __device__ __forceinline__ void cp_async16(uint32_t dst, const void* src) {
    asm volatile("cp.async.cg.shared.global [%0], [%1], 16;"
                 :: "r"(dst), "l"(src));
}
static __device__ __forceinline__ void cp_commit() {
    asm volatile("cp.async.commit_group;" ::: "memory");
}

// packed fp32 pair helpers (Blackwell FFMA2 path)
#define PACK2(o, lo, hi)  asm("mov.b64 %0, {%1, %2};" : "=l"(o) : "f"(lo), "f"(hi))
#define UNPACK2(lo, hi, i) asm("mov.b64 {%0, %1}, %2;" : "=f"(lo), "=f"(hi) : "l"(i))
#define ADDX2(o, a, b)     asm("add.rn.f32x2 %0, %1, %2;" : "=l"(o) : "l"(a), "l"(b))
#define FMAX2(o, a, b, c)  asm("fma.rn.f32x2 %0, %1, %2, %3;" : "=l"(o) : "l"(a), "l"(b), "l"(c))

// fp8 pack: lo = x, hi = y (cvt packs 2nd src operand into low half)
static __device__ __forceinline__ uint16_t f2_to_e4m3x2(float x, float y) {
    uint16_t r;
    asm("cvt.rn.satfinite.e4m3x2.f32 %0, %1, %2;" : "=h"(r) : "f"(y), "f"(x));
    return r;
}
static __device__ __forceinline__ float2 e4m3x2_to_f2(uint16_t q) {
    uint32_t h2;
    asm("cvt.rn.f16x2.e4m3x2 %0, %1;" : "=r"(h2) : "h"(q));
    return __half22float2(*(__half2*)&h2);
}

// ---------------------------------------------------------------------------
// K1: fused prep + diag. One warp per pair (i, i+4096).
// Converts to e4m3, computes |x|^2 from dequantized fp8 (consistent with mma),
// fp32 diagonal for the pos term.
// ---------------------------------------------------------------------------
__global__ void prep_kernel(const float* __restrict__ feat) {
    int w = threadIdx.x >> 5;
    int lane = threadIdx.x & 31;
    int p = blockIdx.x * 8 + w;           // 0..4095
    if (blockIdx.x == 0 && threadIdx.x == 0) {
        g_part[0] = 0.f; g_part[1] = 0.f; g_cnt = 0u;
    }
    if (p >= BHALF) return;
    float4 v1 = ((const float4*)(feat + (size_t)p * KDIM))[lane];
    float4 v2 = ((const float4*)(feat + (size_t)(p + BHALF) * KDIM))[lane];

    uint16_t q1a = f2_to_e4m3x2(v1.x, v1.y), q1b = f2_to_e4m3x2(v1.z, v1.w);
    uint16_t q2a = f2_to_e4m3x2(v2.x, v2.y), q2b = f2_to_e4m3x2(v2.z, v2.w);
    ((uint32_t*)(g_X8 + (size_t)p * KDIM))[lane] = (uint32_t)q1a | ((uint32_t)q1b << 16);
    ((uint32_t*)(g_X8 + (size_t)(p + BHALF) * KDIM))[lane] = (uint32_t)q2a | ((uint32_t)q2b << 16);

    float2 r1a = e4m3x2_to_f2(q1a), r1b = e4m3x2_to_f2(q1b);
    float2 r2a = e4m3x2_to_f2(q2a), r2b = e4m3x2_to_f2(q2b);
    float sb1 = r1a.x * r1a.x + r1a.y * r1a.y + r1b.x * r1b.x + r1b.y * r1b.y;
    float sb2 = r2a.x * r2a.x + r2a.y * r2a.y + r2b.x * r2b.x + r2b.y * r2b.y;
    float t1 = v1.x * v1.x + v1.y * v1.y + v1.z * v1.z + v1.w * v1.w;
    float t2 = v2.x * v2.x + v2.y * v2.y + v2.z * v2.z + v2.w * v2.w;
    float sd = v1.x * v2.x + v1.y * v2.y + v1.z * v2.z + v1.w * v2.w;

#pragma unroll
    for (int off = 16; off > 0; off >>= 1) {
        sb1 += __shfl_xor_sync(0xffffffff, sb1, off);
        sb2 += __shfl_xor_sync(0xffffffff, sb2, off);
        t1  += __shfl_xor_sync(0xffffffff, t1, off);
        t2  += __shfl_xor_sync(0xffffffff, t2, off);
        sd  += __shfl_xor_sync(0xffffffff, sd, off);
    }
    if (lane == 0) {
        g_sq[p] = sb1;
        g_sq[p + BHALF] = sb2;
        g_row[p] = 0.f;
        g_row[p + BHALF] = 0.f;
        float d2v = fmaxf(t1 + t2 - 2.f * sd, 0.f);
        g_logdiag[p] = -log1pf(d2v);
    }
}

// ---------------------------------------------------------------------------
// K2: persistent, software-pipelined fp8 pairwise kernel.
// 296 CTAs x 7-8 upper-triangle 128x128 tiles, bi-major; A resident per chunk,
// B double-buffered via cp.async. mma.sync m16n8k32 e4m3 (fp32 accum), fused
// Cauchy epilogue (packed f32x2) with row + column sums.
// fp8 fragments load via ldmatrix in b16 view: each b32 reg = 4 consecutive k.
// ---------------------------------------------------------------------------
#define LDS_STRIDE_B 144   // bytes per smem row: 128 data + 16 pad
#define TILE_BYTES (128 * LDS_STRIDE_B)        // 18432
#define PAIR_SMEM_BYTES (3 * TILE_BYTES)       // A + 2x B = 55296

__global__ void __launch_bounds__(256, 2) pair_kernel() {
    extern __shared__ __align__(16) char dynsm[];
    const uint32_t abase = smem_u32(dynsm);
    const uint32_t bbase0 = abase + TILE_BYTES;
    __shared__ float s_a[128];        // |x|^2 for A rows (raw)
    __shared__ float s_bb[2][128];    // |y|^2 for B rows (raw), per buffer

    const int tid = threadIdx.x;
    const int lane = tid & 31;
    const int wid = tid >> 5;

    // ---- chunk of tiles for this CTA ----
    const int b = blockIdx.x;
    const int start = b * 7 + (b < 8 ? b : 8);
    const int cnt = 7 + (b < 8 ? 1 : 0);
    int bi = 0, rem = start;
    while (rem >= NBLK - bi) { rem -= NBLK - bi; bi++; }
    int bj = bi + rem;

    auto issue_B = [&](int blk, int buf) {
        const char* g = (const char*)(g_X8 + (size_t)blk * 128 * KDIM);
        uint32_t sb = bbase0 + buf * TILE_BYTES;
#pragma unroll
        for (int it = 0; it < 4; it++) {
            int idx = tid + it * 256;          // 0..1023 (16B chunks)
            int r = idx >> 3, c = idx & 7;
            cp_async16(sb + r * LDS_STRIDE_B + c * 16, g + r * 128 + c * 16);
        }
        if (tid < 32)
            cp_async16(smem_u32(&s_bb[buf][0]) + tid * 16,
                       (const char*)(g_sq + blk * 128) + tid * 16);
    };
    auto issue_A = [&](int blk) {
        const char* g = (const char*)(g_X8 + (size_t)blk * 128 * KDIM);
#pragma unroll
        for (int it = 0; it < 4; it++) {
            int idx = tid + it * 256;
            int r = idx >> 3, c = idx & 7;
            cp_async16(abase + r * LDS_STRIDE_B + c * 16, g + r * 128 + c * 16);
        }
        if (tid < 32)
            cp_async16(smem_u32(&s_a[0]) + tid * 16,
                       (const char*)(g_sq + blk * 128) + tid * 16);
    };

    // ---- warp tiling constants: 4 (m) x 2 (n); warp tile = 32 x 64 ----
    const int rowbase = (wid & 3) * 32;
    const int colbase = (wid >> 2) * 64;
    const int lr = lane & 15;
    const int lc = lane >> 4;
    uint32_t aoff[2];
    uint32_t brel[4];
#pragma unroll
    for (int mi = 0; mi < 2; mi++)
        aoff[mi] = abase + (uint32_t)((rowbase + mi * 16 + lr) * LDS_STRIDE_B + lc * 16);
#pragma unroll
    for (int nq = 0; nq < 4; nq++)
        brel[nq] = (uint32_t)((colbase + nq * 16 + lr) * LDS_STRIDE_B + lc * 16);

    const int qr = lane >> 2;
    const int qc = (lane & 3) * 2;

    // ---- prime: A(bi) + B(bj) into buf 0 ----
    issue_A(bi);
    issue_B(bj, 0);
    cp_commit();
    bool need_cur = false;

    for (int i = 0; i < cnt; i++) {
        const int cur = i & 1;
        int nbi = bi, nbj = bj + 1;
        if (nbj == NBLK) { nbi++; nbj = nbi; }
        const bool have_next = (i + 1 < cnt);
        const bool same_bi = have_next && (nbi == bi);

        if (i > 0) __syncthreads();   // nobody still reads any buffer
        if (need_cur) {               // bi crossing: load A(bi)+B(bj,cur)
            issue_A(bi);
            issue_B(bj, cur);
            cp_commit();
        }
        if (same_bi) {                // prefetch next B during compute
            issue_B(nbj, cur ^ 1);
            cp_commit();
            asm volatile("cp.async.wait_group 1;" ::: "memory");
        } else {
            asm volatile("cp.async.wait_group 0;" ::: "memory");
        }
        __syncthreads();
        need_cur = have_next && (nbi != bi);

        const uint32_t bb = bbase0 + cur * TILE_BYTES;
        const float* s_b = s_bb[cur];

        // ---- mma over K=128 fp8 (4 steps of 32) ----
        float acc[2][8][4];
#pragma unroll
        for (int mi = 0; mi < 2; mi++)
#pragma unroll
            for (int ni = 0; ni < 8; ni++)
#pragma unroll
                for (int r = 0; r < 4; r++) acc[mi][ni][r] = 0.f;

#pragma unroll
        for (int ks = 0; ks < 4; ks++) {
            uint32_t a[2][4];
            uint32_t bfr[8][2];
#pragma unroll
            for (int mi = 0; mi < 2; mi++) {
                asm volatile("ldmatrix.sync.aligned.m8n8.x4.shared.b16 {%0,%1,%2,%3}, [%4];"
                             : "=r"(a[mi][0]), "=r"(a[mi][1]), "=r"(a[mi][2]), "=r"(a[mi][3])
                             : "r"(aoff[mi] + ks * 32));
            }
#pragma unroll
            for (int nq = 0; nq < 4; nq++) {
                uint32_t r0, r1, r2, r3;
                asm volatile("ldmatrix.sync.aligned.m8n8.x4.shared.b16 {%0,%1,%2,%3}, [%4];"
                             : "=r"(r0), "=r"(r1), "=r"(r2), "=r"(r3)
                             : "r"(bb + brel[nq] + ks * 32));
                bfr[nq * 2 + 0][0] = r0; bfr[nq * 2 + 1][0] = r1;
                bfr[nq * 2 + 0][1] = r2; bfr[nq * 2 + 1][1] = r3;
            }
#pragma unroll
            for (int mi = 0; mi < 2; mi++)
#pragma unroll
                for (int ni = 0; ni < 8; ni++) {
                    asm volatile(
                        "mma.sync.aligned.m16n8k32.row.col.f32.e4m3.e4m3.f32 "
                        "{%0,%1,%2,%3}, {%4,%5,%6,%7}, {%8,%9}, {%0,%1,%2,%3};"
                        : "+f"(acc[mi][ni][0]), "+f"(acc[mi][ni][1]),
                          "+f"(acc[mi][ni][2]), "+f"(acc[mi][ni][3])
                        : "r"(a[mi][0]), "r"(a[mi][1]), "r"(a[mi][2]), "r"(a[mi][3]),
                          "r"(bfr[ni][0]), "r"(bfr[ni][1]));
                }
        }

        // ---- epilogue (packed f32x2): k = 1/(1 + |x|^2 + |y|^2 - 2 x.y) ----
        const bool offdiag = (bi != bj);
        ull M2, ZER;
        PACK2(M2, -2.f, -2.f);
        PACK2(ZER, 0.f, 0.f);
        ull apk[2][2];
#pragma unroll
        for (int mi = 0; mi < 2; mi++) {
            float a0 = 1.f + s_a[rowbase + mi * 16 + qr];
            float a1 = 1.f + s_a[rowbase + mi * 16 + qr + 8];
            PACK2(apk[mi][0], a0, a0);
            PACK2(apk[mi][1], a1, a1);
        }
        ull rsp[2][2] = {{ZER, ZER}, {ZER, ZER}};

#pragma unroll
        for (int ni = 0; ni < 8; ni++) {
            float2 bp = *(const float2*)&s_b[colbase + ni * 8 + qc];
            ull bpk; PACK2(bpk, bp.x, bp.y);
            ull csp = ZER;
#pragma unroll
            for (int mi = 0; mi < 2; mi++) {
                ull t0, t1;
                ADDX2(t0, apk[mi][0], bpk);
                ADDX2(t1, apk[mi][1], bpk);
                ull a01, a23;
                PACK2(a01, acc[mi][ni][0], acc[mi][ni][1]);
                PACK2(a23, acc[mi][ni][2], acc[mi][ni][3]);
                ull d0, d1;
                FMAX2(d0, a01, M2, t0);
                FMAX2(d1, a23, M2, t1);
                float f00, f01, f10, f11;
                UNPACK2(f00, f01, d0);
                UNPACK2(f10, f11, d1);
                ull k01, k23;
                PACK2(k01, rcp_approx(f00), rcp_approx(f01));
                PACK2(k23, rcp_approx(f10), rcp_approx(f11));
                ADDX2(rsp[mi][0], rsp[mi][0], k01);
                ADDX2(rsp[mi][1], rsp[mi][1], k23);
                ADDX2(csp, csp, k01);
                ADDX2(csp, csp, k23);
            }
            if (offdiag) {
                float cs0, cs1;
                UNPACK2(cs0, cs1, csp);
                cs0 += __shfl_xor_sync(0xffffffff, cs0, 4);
                cs1 += __shfl_xor_sync(0xffffffff, cs1, 4);
                cs0 += __shfl_xor_sync(0xffffffff, cs0, 8);
                cs1 += __shfl_xor_sync(0xffffffff, cs1, 8);
                cs0 += __shfl_xor_sync(0xffffffff, cs0, 16);
                cs1 += __shfl_xor_sync(0xffffffff, cs1, 16);
                if (lane < 4) {
                    int cg = bj * 128 + colbase + ni * 8 + qc;
                    atomicAdd(g_row + cg, cs0);
                    atomicAdd(g_row + cg + 1, cs1);
                }
            }
        }
#pragma unroll
        for (int mi = 0; mi < 2; mi++) {
            float rs0, rs1, x, y;
            UNPACK2(x, y, rsp[mi][0]); rs0 = x + y;
            UNPACK2(x, y, rsp[mi][1]); rs1 = x + y;
            rs0 += __shfl_xor_sync(0xffffffff, rs0, 1);
            rs1 += __shfl_xor_sync(0xffffffff, rs1, 1);
            rs0 += __shfl_xor_sync(0xffffffff, rs0, 2);
            rs1 += __shfl_xor_sync(0xffffffff, rs1, 2);
            if ((lane & 3) == 0) {
                int r0 = bi * 128 + rowbase + mi * 16 + qr;
                atomicAdd(g_row + r0, rs0);
                atomicAdd(g_row + r0 + 8, rs1);
            }
        }

        bi = nbi; bj = nbj;
    }
}

// ---------------------------------------------------------------------------
// K3: parallel finalize.
// ---------------------------------------------------------------------------
__global__ void finalize_kernel(float* out) {
    const int tid = threadIdx.x;
    const int b = blockIdx.x;
    int row = b * 512 + tid;                 // 16*512 = 8192
    float an = __logf(g_row[row] - 1.0f);
    float ap = (tid < 256) ? g_logdiag[b * 256 + tid] : 0.f;
#pragma unroll
    for (int off = 16; off > 0; off >>= 1) {
        an += __shfl_xor_sync(0xffffffff, an, off);
        ap += __shfl_xor_sync(0xffffffff, ap, off);
    }
    __shared__ float sn[16], sp[16];
    int wid = tid >> 5, lane = tid & 31;
    if (lane == 0) { sn[wid] = an; sp[wid] = ap; }
    __syncthreads();
    if (tid == 0) {
        float tn = 0.f, tp = 0.f;
#pragma unroll
        for (int i = 0; i < 16; i++) { tn += sn[i]; tp += sp[i]; }
        atomicAdd(&g_part[0], tn);
        atomicAdd(&g_part[1], tp);
        __threadfence();
        unsigned int done = atomicAdd(&g_cnt, 1u);
        if (done == 15u) {
            float neg = *((volatile float*)&g_part[0]) / (2.0f * (float)BHALF);
            float pos = *((volatile float*)&g_part[1]) / (float)BHALF;
            out[0] = neg - pos;   // -(pos - neg)
        }
    }
}

// ---------------------------------------------------------------------------
extern "C" void kernel_launch(void* const* d_in, const int* in_sizes, int n_in,
                              void* d_out, int out_size) {
    const float* feat = (const float*)d_in[0];
    float* out = (float*)d_out;

    cudaFuncSetAttribute(pair_kernel,
                         cudaFuncAttributeMaxDynamicSharedMemorySize,
                         PAIR_SMEM_BYTES);

    prep_kernel<<<BHALF / 8, 256>>>(feat);
    pair_kernel<<<PCTAS, 256, PAIR_SMEM_BYTES>>>();
    finalize_kernel<<<16, 512>>>(out);
}